// round 17
// baseline (speedup 1.0000x reference)
#include <cuda_runtime.h>
#include <cstdint>

#define N_IN    50000
#define C_DIM   64
#define T_DIM   8
#define E_EDGES 800000
#define N_OUT   50000
#define F_DIM   64
#define KDIM    512   // T*C

#define SCAN_BLK   1024
#define SCAN_NBLK  ((N_OUT + SCAN_BLK - 1) / SCAN_BLK)   // 49

// ---------------- scratch (device globals; no allocation allowed) ----------------
__device__ int   g_idx64;               // 1 if indices are int64, 0 if int32
__device__ int   g_counts[N_OUT];
__device__ int   g_offsets[N_OUT + 1];
__device__ int   g_cursor[N_OUT];
__device__ int2  g_perm2[E_EDGES];      // (edge id, idx_in) packed
__device__ int   g_blocksums[64];
__device__ float g_edgeT[(size_t)E_EDGES * T_DIM];   // 25.6 MB, edge-major [e][t]
__device__ float g_agg[(size_t)N_OUT * KDIM];        // 102.4 MB

// ---------------- index accessors (dtype-robust) ----------------
__device__ __forceinline__ int idx_out_of(const int* __restrict__ idx, int e, int is64) {
    return is64 ? idx[4 * e] : idx[2 * e];
}
__device__ __forceinline__ int idx_in_of(const int* __restrict__ idx, int e, int is64) {
    return is64 ? idx[4 * e + 2] : idx[2 * e + 1];
}

// ---------------- K1: zero histogram + parallel dtype probe ----------------
__global__ void zero_probe_kernel(const int* __restrict__ idx) {
    __shared__ int s_nz;
    int i = blockIdx.x * blockDim.x + threadIdx.x;
    if (i < N_OUT) g_counts[i] = 0;
    if (blockIdx.x == 0) {
        if (threadIdx.x == 0) s_nz = 0;
        __syncthreads();
        if (threadIdx.x < 128) {
            int v = idx[2 * threadIdx.x + 1];   // odd words: 0 iff int64
            if (v != 0) atomicOr(&s_nz, 1);
        }
        __syncthreads();
        if (threadIdx.x == 0) g_idx64 = (s_nz == 0) ? 1 : 0;
    }
}

// ---------------- K2: fused histogram + transpose edge features --------------
__global__ void hist_transpose_kernel(const float* __restrict__ edgef,
                                      const int* __restrict__ idx) {
    int e = blockIdx.x * blockDim.x + threadIdx.x;
    if (e < E_EDGES) {
        atomicAdd(&g_counts[idx_out_of(idx, e, g_idx64)], 1);
        float v[T_DIM];
        #pragma unroll
        for (int t = 0; t < T_DIM; t++)
            v[t] = edgef[(size_t)t * E_EDGES + e];
        float4* dst = (float4*)&g_edgeT[(size_t)e * T_DIM];
        dst[0] = make_float4(v[0], v[1], v[2], v[3]);
        dst[1] = make_float4(v[4], v[5], v[6], v[7]);
    }
}

// ---------------- K3: parallel scan, pass 1 (local scan + block sums) --------
__global__ __launch_bounds__(SCAN_BLK) void scan_partial_kernel() {
    __shared__ int warp_sums[32];
    const int tid = threadIdx.x;
    const int b   = blockIdx.x;
    const int i   = b * SCAN_BLK + tid;
    int v = (i < N_OUT) ? g_counts[i] : 0;
    int x = v;
    #pragma unroll
    for (int d = 1; d < 32; d <<= 1) {
        int y = __shfl_up_sync(0xffffffffu, x, d);
        if ((tid & 31) >= d) x += y;
    }
    if ((tid & 31) == 31) warp_sums[tid >> 5] = x;
    __syncthreads();
    if (tid < 32) {
        int s = warp_sums[tid];
        #pragma unroll
        for (int d = 1; d < 32; d <<= 1) {
            int y = __shfl_up_sync(0xffffffffu, s, d);
            if (tid >= d) s += y;
        }
        warp_sums[tid] = s;
    }
    __syncthreads();
    int warp_prefix = (tid >= 32) ? warp_sums[(tid >> 5) - 1] : 0;
    int incl = warp_prefix + x;
    if (i < N_OUT) g_offsets[i] = incl - v;
    if (tid == SCAN_BLK - 1) g_blocksums[b] = incl;
}

// ---------------- K4: fused pass 2+3 (every block scans the 49 sums) ---------
__global__ __launch_bounds__(SCAN_BLK) void scan_add_fused_kernel() {
    __shared__ int s[64];
    const int tid = threadIdx.x;
    const int b   = blockIdx.x;
    if (tid < 64) s[tid] = (tid < SCAN_NBLK) ? g_blocksums[tid] : 0;
    __syncthreads();
    #pragma unroll
    for (int d = 1; d < 64; d <<= 1) {
        int y = 0;
        if (tid < 64 && tid >= d) y = s[tid - d];
        __syncthreads();
        if (tid < 64) s[tid] += y;
        __syncthreads();
    }
    int blockoff = (b > 0) ? s[b - 1] : 0;
    const int i = b * SCAN_BLK + tid;
    if (i < N_OUT) {
        int off = g_offsets[i] + blockoff;
        g_offsets[i] = off;
        g_cursor[i]  = off;
    }
    if (b == SCAN_NBLK - 1 && tid == 0) g_offsets[N_OUT] = s[SCAN_NBLK - 1];
}

// ---------------- K5: scatter (edge, idx_in) pairs into CSR slots ------------
__global__ void fill_perm_kernel(const int* __restrict__ idx) {
    int e = blockIdx.x * blockDim.x + threadIdx.x;
    if (e < E_EDGES) {
        int is64 = g_idx64;
        int o   = idx_out_of(idx, e, is64);
        int nin = idx_in_of(idx, e, is64);
        int p = atomicAdd(&g_cursor[o], 1);
        g_perm2[p] = make_int2(e, nin);
    }
}

// ---------------- K6: pull phase — one warp per node ----------------
__global__ __launch_bounds__(256) void pull_kernel(const float* __restrict__ node) {
    int w = blockIdx.x * 8 + (threadIdx.x >> 5);
    int lane = threadIdx.x & 31;
    int s    = g_offsets[w];
    int send = g_offsets[w + 1];

    float accx[T_DIM], accy[T_DIM];
    #pragma unroll
    for (int t = 0; t < T_DIM; t++) { accx[t] = 0.f; accy[t] = 0.f; }

    int p = s;
    for (; p + 2 <= send; p += 2) {
        int2 en0 = g_perm2[p];
        int2 en1 = g_perm2[p + 1];
        float4 wa0 = *(const float4*)&g_edgeT[(size_t)en0.x * T_DIM];
        float4 wb0 = *(const float4*)&g_edgeT[(size_t)en0.x * T_DIM + 4];
        float4 wa1 = *(const float4*)&g_edgeT[(size_t)en1.x * T_DIM];
        float4 wb1 = *(const float4*)&g_edgeT[(size_t)en1.x * T_DIM + 4];
        float2 nv0 = *(const float2*)(node + (size_t)en0.y * 64 + lane * 2);
        float2 nv1 = *(const float2*)(node + (size_t)en1.y * 64 + lane * 2);
        float w0[8] = { wa0.x, wa0.y, wa0.z, wa0.w, wb0.x, wb0.y, wb0.z, wb0.w };
        float w1[8] = { wa1.x, wa1.y, wa1.z, wa1.w, wb1.x, wb1.y, wb1.z, wb1.w };
        #pragma unroll
        for (int t = 0; t < T_DIM; t++) {
            accx[t] += w0[t] * nv0.x + w1[t] * nv1.x;
            accy[t] += w0[t] * nv0.y + w1[t] * nv1.y;
        }
    }
    if (p < send) {
        int2 en = g_perm2[p];
        float4 wa = *(const float4*)&g_edgeT[(size_t)en.x * T_DIM];
        float4 wb = *(const float4*)&g_edgeT[(size_t)en.x * T_DIM + 4];
        float2 nv = *(const float2*)(node + (size_t)en.y * 64 + lane * 2);
        float wv[8] = { wa.x, wa.y, wa.z, wa.w, wb.x, wb.y, wb.z, wb.w };
        #pragma unroll
        for (int t = 0; t < T_DIM; t++) {
            accx[t] += wv[t] * nv.x;
            accy[t] += wv[t] * nv.y;
        }
    }

    size_t base = (size_t)w * KDIM + lane * 2;
    #pragma unroll
    for (int t = 0; t < T_DIM; t++)
        *(float2*)&g_agg[base + t * 64] = make_float2(accx[t], accy[t]);
}

// ---------------- K7: GEMM out = agg(50000x512) @ W(512x64) + bias -----------
// TM=8 x TN=8 per thread, 128 threads/CTA: 64B smem per 64 MACs per thread/kk
// (1.0 B/MAC) so LDS bandwidth no longer binds; FFMA2 issue is the floor.
#define BM 128
#define BN 64
#define BK 16
#define TM 8
#define TN 8
#define NKIT (KDIM / BK)   // 32

__global__ __launch_bounds__(128) void gemm_kernel(
    const float* __restrict__ W,      // (T*C, F) row-major
    const float* __restrict__ bias,
    float* __restrict__ out)
{
    __shared__ float As[2][BK][BM];   // 2 x 8 KB (A transposed)
    __shared__ float Bs[2][BK][BN];   // 2 x 4 KB

    const int tid  = threadIdx.x;     // 0..127
    const int row0 = blockIdx.x * BM;
    const int tx   = tid & 7;         // col group: cols tx*8 .. tx*8+7
    const int ty   = tid >> 3;        // row group: rows ty*8 .. ty*8+7 (0..15)

    // A tile: thread loads its whole row (tid) = 4 float4s
    const int gr_a = row0 + tid;
    // B tile: 256 float4s, 2 per thread
    const int kr_b0 = (tid * 2) >> 4,     c4_b0 = (tid * 2) & 15;
    const int kr_b1 = (tid * 2 + 1) >> 4, c4_b1 = (tid * 2 + 1) & 15;

    unsigned long long acc2[TM / 2][TN];   // 4 row-pairs x 8 cols
    #pragma unroll
    for (int i = 0; i < TM / 2; i++)
        #pragma unroll
        for (int j = 0; j < TN; j++) acc2[i][j] = 0ull;

    float4 pa[4], pb0, pb1;

    // prologue: load tile 0
    #pragma unroll
    for (int i = 0; i < 4; i++) {
        pa[i] = make_float4(0.f, 0.f, 0.f, 0.f);
        if (gr_a < N_OUT)
            pa[i] = *(const float4*)&g_agg[(size_t)gr_a * KDIM + i * 4];
    }
    pb0 = *(const float4*)&W[(size_t)kr_b0 * 64 + c4_b0 * 4];
    pb1 = *(const float4*)&W[(size_t)kr_b1 * 64 + c4_b1 * 4];

    #pragma unroll
    for (int i = 0; i < 4; i++) {
        As[0][i * 4 + 0][tid] = pa[i].x;
        As[0][i * 4 + 1][tid] = pa[i].y;
        As[0][i * 4 + 2][tid] = pa[i].z;
        As[0][i * 4 + 3][tid] = pa[i].w;
    }
    *(float4*)&Bs[0][kr_b0][c4_b0 * 4] = pb0;
    *(float4*)&Bs[0][kr_b1][c4_b1 * 4] = pb1;
    __syncthreads();

    for (int it = 0; it < NKIT; it++) {
        const int buf = it & 1;

        // prefetch next tile (overlaps compute)
        if (it + 1 < NKIT) {
            const int k0n = (it + 1) * BK;
            #pragma unroll
            for (int i = 0; i < 4; i++) {
                pa[i] = make_float4(0.f, 0.f, 0.f, 0.f);
                if (gr_a < N_OUT)
                    pa[i] = *(const float4*)&g_agg[(size_t)gr_a * KDIM + k0n + i * 4];
            }
            pb0 = *(const float4*)&W[(size_t)(k0n + kr_b0) * 64 + c4_b0 * 4];
            pb1 = *(const float4*)&W[(size_t)(k0n + kr_b1) * 64 + c4_b1 * 4];
        }

        #pragma unroll
        for (int kk = 0; kk < BK; kk++) {
            ulonglong2 aq0 = *(const ulonglong2*)&As[buf][kk][ty * TM];
            ulonglong2 aq1 = *(const ulonglong2*)&As[buf][kk][ty * TM + 4];
            unsigned long long a2[4] = { aq0.x, aq0.y, aq1.x, aq1.y };
            float4 b0 = *(const float4*)&Bs[buf][kk][tx * TN];
            float4 b1 = *(const float4*)&Bs[buf][kk][tx * TN + 4];
            unsigned long long b2[8];
            asm("mov.b64 %0, {%1, %1};" : "=l"(b2[0]) : "r"(__float_as_uint(b0.x)));
            asm("mov.b64 %0, {%1, %1};" : "=l"(b2[1]) : "r"(__float_as_uint(b0.y)));
            asm("mov.b64 %0, {%1, %1};" : "=l"(b2[2]) : "r"(__float_as_uint(b0.z)));
            asm("mov.b64 %0, {%1, %1};" : "=l"(b2[3]) : "r"(__float_as_uint(b0.w)));
            asm("mov.b64 %0, {%1, %1};" : "=l"(b2[4]) : "r"(__float_as_uint(b1.x)));
            asm("mov.b64 %0, {%1, %1};" : "=l"(b2[5]) : "r"(__float_as_uint(b1.y)));
            asm("mov.b64 %0, {%1, %1};" : "=l"(b2[6]) : "r"(__float_as_uint(b1.z)));
            asm("mov.b64 %0, {%1, %1};" : "=l"(b2[7]) : "r"(__float_as_uint(b1.w)));
            #pragma unroll
            for (int i = 0; i < 4; i++)
                #pragma unroll
                for (int j = 0; j < 8; j++)
                    asm("fma.rn.f32x2 %0, %1, %2, %0;"
                        : "+l"(acc2[i][j]) : "l"(a2[i]), "l"(b2[j]));
        }

        if (it + 1 < NKIT) {
            const int nb = buf ^ 1;
            #pragma unroll
            for (int i = 0; i < 4; i++) {
                As[nb][i * 4 + 0][tid] = pa[i].x;
                As[nb][i * 4 + 1][tid] = pa[i].y;
                As[nb][i * 4 + 2][tid] = pa[i].z;
                As[nb][i * 4 + 3][tid] = pa[i].w;
            }
            *(float4*)&Bs[nb][kr_b0][c4_b0 * 4] = pb0;
            *(float4*)&Bs[nb][kr_b1][c4_b1 * 4] = pb1;
        }
        __syncthreads();
    }

    float4 bv0 = *(const float4*)&bias[tx * TN];
    float4 bv1 = *(const float4*)&bias[tx * TN + 4];
    float bb[8] = { bv0.x, bv0.y, bv0.z, bv0.w, bv1.x, bv1.y, bv1.z, bv1.w };
    #pragma unroll
    for (int i = 0; i < TM / 2; i++) {
        int r0 = row0 + ty * TM + 2 * i;
        float lo[8], hi[8];
        #pragma unroll
        for (int j = 0; j < 8; j++) {
            unsigned int l, h;
            asm("mov.b64 {%0, %1}, %2;" : "=r"(l), "=r"(h) : "l"(acc2[i][j]));
            lo[j] = __uint_as_float(l) + bb[j];
            hi[j] = __uint_as_float(h) + bb[j];
        }
        if (r0 < N_OUT) {
            *(float4*)&out[(size_t)r0 * F_DIM + tx * TN]     = make_float4(lo[0], lo[1], lo[2], lo[3]);
            *(float4*)&out[(size_t)r0 * F_DIM + tx * TN + 4] = make_float4(lo[4], lo[5], lo[6], lo[7]);
        }
        if (r0 + 1 < N_OUT) {
            *(float4*)&out[(size_t)(r0 + 1) * F_DIM + tx * TN]     = make_float4(hi[0], hi[1], hi[2], hi[3]);
            *(float4*)&out[(size_t)(r0 + 1) * F_DIM + tx * TN + 4] = make_float4(hi[4], hi[5], hi[6], hi[7]);
        }
    }
}

// ---------------- launch ----------------
extern "C" void kernel_launch(void* const* d_in, const int* in_sizes, int n_in,
                              void* d_out, int out_size)
{
    const float* node  = nullptr;
    const float* edgef = nullptr;
    const int*   idx   = nullptr;
    const float* W     = nullptr;
    const float* bias  = nullptr;

    for (int i = 0; i < n_in; i++) {
        switch (in_sizes[i]) {
            case N_IN * C_DIM:          node  = (const float*)d_in[i]; break;
            case T_DIM * E_EDGES:       edgef = (const float*)d_in[i]; break;
            case E_EDGES * 2:           idx   = (const int*)d_in[i];   break;
            case T_DIM * C_DIM * F_DIM: W     = (const float*)d_in[i]; break;
            case F_DIM:                 bias  = (const float*)d_in[i]; break;
            default: break;
        }
    }
    float* out = (float*)d_out;

    zero_probe_kernel<<<(N_OUT + 255) / 256, 256>>>(idx);
    hist_transpose_kernel<<<(E_EDGES + 255) / 256, 256>>>(edgef, idx);
    scan_partial_kernel<<<SCAN_NBLK, SCAN_BLK>>>();
    scan_add_fused_kernel<<<SCAN_NBLK, SCAN_BLK>>>();
    fill_perm_kernel<<<(E_EDGES + 255) / 256, 256>>>(idx);
    pull_kernel<<<N_OUT / 8, 256>>>(node);
    gemm_kernel<<<(N_OUT + BM - 1) / BM, 128>>>(W, bias, out);
}